// round 6
// baseline (speedup 1.0000x reference)
#include <cuda_runtime.h>
#include <cstdint>

#define NROWS 4194304
#define HALFN (NROWS / 2)
#define DVAL 8
#define BLOCK 256
#define GRID (HALFN / BLOCK)   // 8192
#define BIGKNOCK 1.0e38f
#define DEAD_THRESH 1.0e30f

__device__ float    g_scratch = 0.0f;
__device__ unsigned g_count   = 0u;

// set.eq returns 1.0f / 0.0f in a float register (single FSET, alu pipe)
__device__ __forceinline__ float fset_eq(float a, float b) {
    float r;
    asm("set.eq.f32.f32 %0, %1, %2;" : "=f"(r) : "f"(a), "f"(b));
    return r;
}
// set.ne (a != b) -> 1.0f / 0.0f
__device__ __forceinline__ float fset_ne(float a, float b) {
    float r;
    asm("set.ne.f32.f32 %0, %1, %2;" : "=f"(r) : "f"(a), "f"(b));
    return r;
}

__device__ __forceinline__ float row_loss(float4 ov0, float4 ov1, float4 tv0, float4 tv1) {
    float t[8] = {tv0.x, tv0.y, tv0.z, tv0.w, tv1.x, tv1.y, tv1.z, tv1.w};
    // live diffs vs current target column; advanced by delta each step
    float d[8] = {ov0.x - t[0], ov0.y - t[0], ov0.z - t[0], ov0.w - t[0],
                  ov1.x - t[0], ov1.y - t[0], ov1.z - t[0], ov1.w - t[0]};

    float acc = 0.0f;
    #pragma unroll
    for (int i = 0; i < DVAL; i++) {
        float tc = t[i];

        // min |d_j| via FMNMX tree (|src| modifier is free)
        float m01 = fminf(fabsf(d[0]), fabsf(d[1]));
        float m23 = fminf(fabsf(d[2]), fabsf(d[3]));
        float m45 = fminf(fabsf(d[4]), fabsf(d[5]));
        float m67 = fminf(fabsf(d[6]), fabsf(d[7]));
        float bestd = fminf(fminf(m01, m23), fminf(m45, m67));

        // targets==IGNORE(0) -> zero contribution: multiply by set.ne mask
        // (1 alu + 1 fma instead of FSETP+FSEL on the busy alu pipe).
        float w = bestd * fset_ne(tc, 0.0f);
        // All-dead (exact-tie double-knockouts) only possible from step 4 on.
        if (i >= 4)
            w = (bestd < DEAD_THRESH) ? w : 0.0f;
        acc = fmaf(w, w, acc);

        // knockout (value match) folded into delta-advance on the fma pipe
        if (i < DVAL - 1) {
            float delta = tc - t[i + 1];
            #pragma unroll
            for (int j = 0; j < DVAL; j++) {
                float eq = fset_eq(fabsf(d[j]), bestd);
                d[j] = fmaf(eq, BIGKNOCK, d[j] + delta);
            }
        }
    }
    return acc;
}

__global__ void __launch_bounds__(BLOCK)
multidepth_mse_kernel(const float* __restrict__ outputs,
                      const float* __restrict__ targets,
                      float* __restrict__ out) {
    int tid = blockIdx.x * BLOCK + threadIdx.x;

    const float4* ob = reinterpret_cast<const float4*>(outputs);
    const float4* tb = reinterpret_cast<const float4*>(targets);

    size_t rA = (size_t)tid * 2;
    size_t rB = (size_t)(tid + HALFN) * 2;

    // Front-batch 8 x LDG.128 for MLP
    float4 oA0 = ob[rA], oA1 = ob[rA + 1], tA0 = tb[rA], tA1 = tb[rA + 1];
    float4 oB0 = ob[rB], oB1 = ob[rB + 1], tB0 = tb[rB], tB1 = tb[rB + 1];

    float acc = row_loss(oA0, oA1, tA0, tA1)
              + row_loss(oB0, oB1, tB0, tB1);

    // warp reduction
    #pragma unroll
    for (int off = 16; off > 0; off >>= 1)
        acc += __shfl_down_sync(0xffffffffu, acc, off);

    __shared__ float warp_sums[BLOCK / 32];
    int lane = threadIdx.x & 31;
    int wid  = threadIdx.x >> 5;
    if (lane == 0) warp_sums[wid] = acc;
    __syncthreads();

    if (wid == 0) {
        acc = (lane < BLOCK / 32) ? warp_sums[lane] : 0.0f;
        #pragma unroll
        for (int off = 16; off > 0; off >>= 1)
            acc += __shfl_down_sync(0xffffffffu, acc, off);
        if (lane == 0) {
            // Single-kernel finish: last block to arrive publishes the result
            // and resets scratch state for the next (graph-replayed) launch.
            float old = atomicAdd(&g_scratch, acc);
            __threadfence();
            unsigned ticket = atomicInc(&g_count, GRID - 1);  // wraps to 0 on last
            if (ticket == GRID - 1) {
                const float inv_total = 1.0f / (float)((long long)NROWS * DVAL);
                out[0] = (old + acc) * inv_total;
                g_scratch = 0.0f;  // visible before next launch (kernel boundary)
            }
        }
    }
}

extern "C" void kernel_launch(void* const* d_in, const int* in_sizes, int n_in,
                              void* d_out, int out_size) {
    const float* outputs = (const float*)d_in[0];
    const float* targets = (const float*)d_in[1];
    float* out = (float*)d_out;

    multidepth_mse_kernel<<<GRID, BLOCK>>>(outputs, targets, out);
}

// round 7
// speedup vs baseline: 1.0077x; 1.0077x over previous
#include <cuda_runtime.h>
#include <cstdint>

#define NROWS 4194304
#define HALFN (NROWS / 2)
#define DVAL 8
#define BLOCK 256
#define GRID (HALFN / BLOCK)   // 8192
#define BIGKNOCK 1.0e38f
#define DEAD_THRESH 1.0e30f

__device__ float    g_scratch = 0.0f;
__device__ unsigned g_count   = 0u;

// set.eq returns 1.0f / 0.0f in a float register (single FSET, alu pipe)
__device__ __forceinline__ float fset_eq(float a, float b) {
    float r;
    asm("set.eq.f32.f32 %0, %1, %2;" : "=f"(r) : "f"(a), "f"(b));
    return r;
}
// set.ne (a != b) -> 1.0f / 0.0f
__device__ __forceinline__ float fset_ne(float a, float b) {
    float r;
    asm("set.ne.f32.f32 %0, %1, %2;" : "=f"(r) : "f"(a), "f"(b));
    return r;
}

__device__ __forceinline__ float row_loss(float4 ov0, float4 ov1, float4 tv0, float4 tv1) {
    float o[8] = {ov0.x, ov0.y, ov0.z, ov0.w, ov1.x, ov1.y, ov1.z, ov1.w};
    float t[8] = {tv0.x, tv0.y, tv0.z, tv0.w, tv1.x, tv1.y, tv1.z, tv1.w};

    float acc = 0.0f;
    #pragma unroll
    for (int i = 0; i < DVAL; i++) {
        float tc = t[i];

        // Fresh diffs every step: exactly single-rounded |o_j - tc|, no drift.
        float d0 = o[0] - tc, d1 = o[1] - tc, d2 = o[2] - tc, d3 = o[3] - tc;
        float d4 = o[4] - tc, d5 = o[5] - tc, d6 = o[6] - tc, d7 = o[7] - tc;

        // min |d_j| via FMNMX tree (|src| modifier is free)
        float m01 = fminf(fabsf(d0), fabsf(d1));
        float m23 = fminf(fabsf(d2), fabsf(d3));
        float m45 = fminf(fabsf(d4), fabsf(d5));
        float m67 = fminf(fabsf(d6), fabsf(d7));
        float bestd = fminf(fminf(m01, m23), fminf(m45, m67));

        // targets==IGNORE(0) -> zero contribution (mask in {0,1}, exact)
        float w = bestd * fset_ne(tc, 0.0f);
        // All-dead (needs >=4 exact-tie double-knockouts) only possible i>=4.
        if (i >= 4)
            w = (bestd < DEAD_THRESH) ? w : 0.0f;
        acc = fmaf(w, w, acc);

        // Value-knockout on o_j itself (fma pipe). Knocked cols sit at ~1e38;
        // |1e38 - tc| == 1e38 exactly, never equals an alive bestd.
        if (i < DVAL - 1) {
            float e0 = fset_eq(fabsf(d0), bestd);
            float e1 = fset_eq(fabsf(d1), bestd);
            float e2 = fset_eq(fabsf(d2), bestd);
            float e3 = fset_eq(fabsf(d3), bestd);
            float e4 = fset_eq(fabsf(d4), bestd);
            float e5 = fset_eq(fabsf(d5), bestd);
            float e6 = fset_eq(fabsf(d6), bestd);
            float e7 = fset_eq(fabsf(d7), bestd);
            o[0] = fmaf(e0, BIGKNOCK, o[0]);
            o[1] = fmaf(e1, BIGKNOCK, o[1]);
            o[2] = fmaf(e2, BIGKNOCK, o[2]);
            o[3] = fmaf(e3, BIGKNOCK, o[3]);
            o[4] = fmaf(e4, BIGKNOCK, o[4]);
            o[5] = fmaf(e5, BIGKNOCK, o[5]);
            o[6] = fmaf(e6, BIGKNOCK, o[6]);
            o[7] = fmaf(e7, BIGKNOCK, o[7]);
        }
    }
    return acc;
}

__global__ void __launch_bounds__(BLOCK)
multidepth_mse_kernel(const float* __restrict__ outputs,
                      const float* __restrict__ targets,
                      float* __restrict__ out) {
    int tid = blockIdx.x * BLOCK + threadIdx.x;

    const float4* ob = reinterpret_cast<const float4*>(outputs);
    const float4* tb = reinterpret_cast<const float4*>(targets);

    size_t rA = (size_t)tid * 2;
    size_t rB = (size_t)(tid + HALFN) * 2;

    // Front-batch 8 x LDG.128 for MLP
    float4 oA0 = ob[rA], oA1 = ob[rA + 1], tA0 = tb[rA], tA1 = tb[rA + 1];
    float4 oB0 = ob[rB], oB1 = ob[rB + 1], tB0 = tb[rB], tB1 = tb[rB + 1];

    float acc = row_loss(oA0, oA1, tA0, tA1)
              + row_loss(oB0, oB1, tB0, tB1);

    // warp reduction
    #pragma unroll
    for (int off = 16; off > 0; off >>= 1)
        acc += __shfl_down_sync(0xffffffffu, acc, off);

    __shared__ float warp_sums[BLOCK / 32];
    int lane = threadIdx.x & 31;
    int wid  = threadIdx.x >> 5;
    if (lane == 0) warp_sums[wid] = acc;
    __syncthreads();

    if (wid == 0) {
        acc = (lane < BLOCK / 32) ? warp_sums[lane] : 0.0f;
        #pragma unroll
        for (int off = 16; off > 0; off >>= 1)
            acc += __shfl_down_sync(0xffffffffu, acc, off);
        if (lane == 0) {
            // Scale partial BEFORE accumulation (small-magnitude adds).
            const float inv_total = 1.0f / (float)((long long)NROWS * DVAL);
            float my = acc * inv_total;
            // Single-kernel finish: last block publishes and resets scratch.
            float old = atomicAdd(&g_scratch, my);
            __threadfence();
            unsigned ticket = atomicInc(&g_count, GRID - 1);  // wraps to 0 on last
            if (ticket == GRID - 1) {
                out[0] = old + my;
                g_scratch = 0.0f;  // visible before next replay (kernel boundary)
            }
        }
    }
}

extern "C" void kernel_launch(void* const* d_in, const int* in_sizes, int n_in,
                              void* d_out, int out_size) {
    const float* outputs = (const float*)d_in[0];
    const float* targets = (const float*)d_in[1];
    float* out = (float*)d_out;

    multidepth_mse_kernel<<<GRID, BLOCK>>>(outputs, targets, out);
}

// round 8
// speedup vs baseline: 1.0983x; 1.0899x over previous
#include <cuda_runtime.h>
#include <cstdint>

#define NROWS 4194304
#define HALFN (NROWS / 2)
#define DVAL 8
#define BLOCK 256
#define GRID (HALFN / BLOCK)   // 8192
#define BIGKNOCK 1.0e38f
#define DEAD_THRESH 1.0e30f

__device__ float    g_scratch = 0.0f;
__device__ unsigned g_count   = 0u;

// set.eq -> 1.0f / 0.0f in a float register (single FSET, alu pipe)
__device__ __forceinline__ float fset_eq(float a, float b) {
    float r;
    asm("set.eq.f32.f32 %0, %1, %2;" : "=f"(r) : "f"(a), "f"(b));
    return r;
}
__device__ __forceinline__ float fset_ne(float a, float b) {
    float r;
    asm("set.ne.f32.f32 %0, %1, %2;" : "=f"(r) : "f"(a), "f"(b));
    return r;
}

// ---- Blackwell packed f32x2 (2 x rn fp32 per instruction, fma pipe) ----
__device__ __forceinline__ uint64_t pack2(float lo, float hi) {
    uint64_t r;
    asm("mov.b64 %0, {%1, %2};" : "=l"(r) : "f"(lo), "f"(hi));
    return r;
}
__device__ __forceinline__ void unpack2(uint64_t p, float& lo, float& hi) {
    asm("mov.b64 {%0, %1}, %2;" : "=f"(lo), "=f"(hi) : "l"(p));
}
__device__ __forceinline__ uint64_t add2(uint64_t a, uint64_t b) {
    uint64_t r;
    asm("add.rn.f32x2 %0, %1, %2;" : "=l"(r) : "l"(a), "l"(b));
    return r;
}
__device__ __forceinline__ uint64_t fma2(uint64_t a, uint64_t b, uint64_t c) {
    uint64_t r;
    asm("fma.rn.f32x2 %0, %1, %2, %3;" : "=l"(r) : "l"(a), "l"(b), "l"(c));
    return r;
}

__device__ __forceinline__ float row_loss(float4 ov0, float4 ov1, float4 tv0, float4 tv1,
                                          uint64_t big2) {
    float t[8] = {tv0.x, tv0.y, tv0.z, tv0.w, tv1.x, tv1.y, tv1.z, tv1.w};
    uint64_t o01 = pack2(ov0.x, ov0.y);
    uint64_t o23 = pack2(ov0.z, ov0.w);
    uint64_t o45 = pack2(ov1.x, ov1.y);
    uint64_t o67 = pack2(ov1.z, ov1.w);

    float acc = 0.0f;
    #pragma unroll
    for (int i = 0; i < DVAL; i++) {
        float tc = t[i];
        uint64_t ntc2 = pack2(-tc, -tc);

        // fresh diffs, packed: identical rounding to scalar FADD
        uint64_t p01 = add2(o01, ntc2);
        uint64_t p23 = add2(o23, ntc2);
        uint64_t p45 = add2(o45, ntc2);
        uint64_t p67 = add2(o67, ntc2);
        float d0, d1, d2, d3, d4, d5, d6, d7;
        unpack2(p01, d0, d1);
        unpack2(p23, d2, d3);
        unpack2(p45, d4, d5);
        unpack2(p67, d6, d7);

        // min |d_j| via FMNMX tree (|src| modifier free)
        float m01 = fminf(fabsf(d0), fabsf(d1));
        float m23 = fminf(fabsf(d2), fabsf(d3));
        float m45 = fminf(fabsf(d4), fabsf(d5));
        float m67 = fminf(fabsf(d6), fabsf(d7));
        float bestd = fminf(fminf(m01, m23), fminf(m45, m67));

        // targets==IGNORE(0) -> zero contribution (mask in {0,1}, exact)
        float w = bestd * fset_ne(tc, 0.0f);
        // all-dead (needs >=4 exact-tie double-knockouts) only possible i>=4
        if (i >= 4)
            w = (bestd < DEAD_THRESH) ? w : 0.0f;
        acc = fmaf(w, w, acc);

        // value-knockout on o_j (packed FFMA2): knocked cols -> ~1e38;
        // |1e38 - tc| == 1e38 exactly, never equals an alive bestd
        if (i < DVAL - 1) {
            uint64_t e01 = pack2(fset_eq(fabsf(d0), bestd), fset_eq(fabsf(d1), bestd));
            uint64_t e23 = pack2(fset_eq(fabsf(d2), bestd), fset_eq(fabsf(d3), bestd));
            uint64_t e45 = pack2(fset_eq(fabsf(d4), bestd), fset_eq(fabsf(d5), bestd));
            uint64_t e67 = pack2(fset_eq(fabsf(d6), bestd), fset_eq(fabsf(d7), bestd));
            o01 = fma2(e01, big2, o01);
            o23 = fma2(e23, big2, o23);
            o45 = fma2(e45, big2, o45);
            o67 = fma2(e67, big2, o67);
        }
    }
    return acc;
}

__global__ void __launch_bounds__(BLOCK)
multidepth_mse_kernel(const float* __restrict__ outputs,
                      const float* __restrict__ targets,
                      float* __restrict__ out) {
    int tid = blockIdx.x * BLOCK + threadIdx.x;

    const float4* ob = reinterpret_cast<const float4*>(outputs);
    const float4* tb = reinterpret_cast<const float4*>(targets);

    size_t rA = (size_t)tid * 2;
    size_t rB = (size_t)(tid + HALFN) * 2;

    // Front-batch 8 x LDG.128, streaming (single-pass data, evict-first)
    float4 oA0 = __ldcs(ob + rA), oA1 = __ldcs(ob + rA + 1);
    float4 tA0 = __ldcs(tb + rA), tA1 = __ldcs(tb + rA + 1);
    float4 oB0 = __ldcs(ob + rB), oB1 = __ldcs(ob + rB + 1);
    float4 tB0 = __ldcs(tb + rB), tB1 = __ldcs(tb + rB + 1);

    uint64_t big2 = pack2(BIGKNOCK, BIGKNOCK);

    float acc = row_loss(oA0, oA1, tA0, tA1, big2)
              + row_loss(oB0, oB1, tB0, tB1, big2);

    // warp reduction
    #pragma unroll
    for (int off = 16; off > 0; off >>= 1)
        acc += __shfl_down_sync(0xffffffffu, acc, off);

    __shared__ float warp_sums[BLOCK / 32];
    int lane = threadIdx.x & 31;
    int wid  = threadIdx.x >> 5;
    if (lane == 0) warp_sums[wid] = acc;
    __syncthreads();

    if (wid == 0) {
        acc = (lane < BLOCK / 32) ? warp_sums[lane] : 0.0f;
        #pragma unroll
        for (int off = 16; off > 0; off >>= 1)
            acc += __shfl_down_sync(0xffffffffu, acc, off);
        if (lane == 0) {
            // scale partial BEFORE accumulation (small-magnitude adds)
            const float inv_total = 1.0f / (float)((long long)NROWS * DVAL);
            float my = acc * inv_total;
            // single-kernel finish: last block publishes and resets scratch
            float old = atomicAdd(&g_scratch, my);
            __threadfence();
            unsigned ticket = atomicInc(&g_count, GRID - 1);  // wraps to 0 on last
            if (ticket == GRID - 1) {
                out[0] = old + my;
                g_scratch = 0.0f;  // visible before next replay (kernel boundary)
            }
        }
    }
}

extern "C" void kernel_launch(void* const* d_in, const int* in_sizes, int n_in,
                              void* d_out, int out_size) {
    const float* outputs = (const float*)d_in[0];
    const float* targets = (const float*)d_in[1];
    float* out = (float*)d_out;

    multidepth_mse_kernel<<<GRID, BLOCK>>>(outputs, targets, out);
}